// round 11
// baseline (speedup 1.0000x reference)
#include <cuda_runtime.h>
#include <math.h>

// h (B=4, T=4096, d=512) fp32, raw_alpha (K=4) fp32 -> out (B, T, K, d) fp32
#define T_DIM 4096
#define D_DIM 512
#define K_DIM 4
#define B_MAX 4
#define CHUNK_L 16
#define NCHUNK (T_DIM / CHUNK_L)   // 256
#define GROUP 16
#define NGROUP (NCHUNK / GROUP)    // 16

// Scratch (allocation-free: __device__ globals)
__device__ float g_rtab[T_DIM * K_DIM];                    // r[t][k] (double-computed)
__device__ float g_E[B_MAX * NCHUNK * D_DIM * K_DIM];      // chunk sums -> local carries (8MB)
__device__ float g_G[B_MAX * NGROUP * D_DIM * K_DIM];      // group sums (512KB)

__device__ __forceinline__ float sigmoid_clip_f(float x) {
    float a = 1.0f / (1.0f + expf(-x));
    return fminf(fmaxf(a, 1e-6f), 1.0f - 1e-6f);
}

__device__ __forceinline__ double sigmoid_clip_d(double x) {
    double a = 1.0 / (1.0 + exp(-x));
    return fmin(fmax(a, 1e-6), 1.0 - 1e-6);
}

// ---------------------------------------------------------------------------
// K1: kB chunk scans, fused with r-table generation (tid < T_DIM does both).
// Thread: (b, c, dd4) — 4 d-lanes x 4 k in regs. alpha computed inline (fp32).
// ---------------------------------------------------------------------------
__global__ __launch_bounds__(256) void kB_fused(const float* __restrict__ h,
                                                const float* __restrict__ raw_alpha,
                                                int Bn) {
    const int DV  = D_DIM / 4;
    int tid = blockIdx.x * blockDim.x + threadIdx.x;

    // --- side job: r-table in double precision (first T_DIM threads) ---
    if (tid < T_DIM) {
        int t = tid;
#pragma unroll
        for (int k = 0; k < K_DIM; k++) {
            double a  = sigmoid_clip_d((double)raw_alpha[k]);
            double la = log(a);
            double p  = exp(la * (double)(t + 1));
            g_rtab[t * K_DIM + k] = (float)((1.0 - a) / (1.0 - p));
        }
    }

    int ddv = tid % DV;
    int c   = (tid / DV) % NCHUNK;
    int b   = tid / (DV * NCHUNK);
    if (b >= Bn) return;
    int dd = ddv * 4;

    float4 a4 = make_float4(sigmoid_clip_f(raw_alpha[0]), sigmoid_clip_f(raw_alpha[1]),
                            sigmoid_clip_f(raw_alpha[2]), sigmoid_clip_f(raw_alpha[3]));

    float4 S0 = make_float4(0.f, 0.f, 0.f, 0.f);
    float4 S1 = S0, S2 = S0, S3 = S0;

    const float4* hp = (const float4*)(h + ((size_t)b * T_DIM + (size_t)c * CHUNK_L) * D_DIM + dd);

#pragma unroll
    for (int j = 0; j < CHUNK_L; j++) {
        float4 h4 = hp[(size_t)j * DV];
        S0.x = fmaf(a4.x, S0.x, h4.x); S0.y = fmaf(a4.y, S0.y, h4.x);
        S0.z = fmaf(a4.z, S0.z, h4.x); S0.w = fmaf(a4.w, S0.w, h4.x);
        S1.x = fmaf(a4.x, S1.x, h4.y); S1.y = fmaf(a4.y, S1.y, h4.y);
        S1.z = fmaf(a4.z, S1.z, h4.y); S1.w = fmaf(a4.w, S1.w, h4.y);
        S2.x = fmaf(a4.x, S2.x, h4.z); S2.y = fmaf(a4.y, S2.y, h4.z);
        S2.z = fmaf(a4.z, S2.z, h4.z); S2.w = fmaf(a4.w, S2.w, h4.z);
        S3.x = fmaf(a4.x, S3.x, h4.w); S3.y = fmaf(a4.y, S3.y, h4.w);
        S3.z = fmaf(a4.z, S3.z, h4.w); S3.w = fmaf(a4.w, S3.w, h4.w);
    }

    float4* Ep = (float4*)&g_E[(((size_t)b * NCHUNK + c) * D_DIM + dd) * K_DIM];
    Ep[0] = S0; Ep[1] = S1; Ep[2] = S2; Ep[3] = S3;
}

// ---------------------------------------------------------------------------
// K2: kC_local — scan within each group of 16 chunks. In place: E[c] becomes
// the local carry into chunk c. Emits group sums to g_G. q = alpha^16 inline.
// ---------------------------------------------------------------------------
__global__ __launch_bounds__(256) void kC_local(const float* __restrict__ raw_alpha, int Bn) {
    int tid = blockIdx.x * blockDim.x + threadIdx.x;
    int dd  = tid % D_DIM;
    int g   = (tid / D_DIM) % NGROUP;
    int b   = tid / (D_DIM * NGROUP);
    if (b >= Bn) return;

    float4 q = make_float4(sigmoid_clip_f(raw_alpha[0]), sigmoid_clip_f(raw_alpha[1]),
                           sigmoid_clip_f(raw_alpha[2]), sigmoid_clip_f(raw_alpha[3]));
#pragma unroll
    for (int s = 0; s < 4; s++) { q.x *= q.x; q.y *= q.y; q.z *= q.z; q.w *= q.w; } // alpha^16

    float4 prev = make_float4(0.f, 0.f, 0.f, 0.f);

#pragma unroll
    for (int i = 0; i < GROUP; i++) {
        int c = g * GROUP + i;
        float4* p = (float4*)&g_E[(((size_t)b * NCHUNK + c) * D_DIM + dd) * K_DIM];
        float4 e = *p;
        *p = prev;
        prev.x = fmaf(q.x, prev.x, e.x);
        prev.y = fmaf(q.y, prev.y, e.y);
        prev.z = fmaf(q.z, prev.z, e.z);
        prev.w = fmaf(q.w, prev.w, e.w);
    }
    *(float4*)&g_G[(((size_t)b * NGROUP + g) * D_DIM + dd) * K_DIM] = prev;
}

// ---------------------------------------------------------------------------
// K3: kD — final scan + normalize + store, with the group carry computed
// INLINE (Horner over g_G, L2-resident). Thread = (b, c, kh, dd4).
// S_init = L_c + carry_g * q^i, q^i and Q=alpha^256 by repeated squaring.
// ---------------------------------------------------------------------------
__global__ __launch_bounds__(256) void kD_final(const float* __restrict__ h,
                                                const float* __restrict__ raw_alpha,
                                                float* __restrict__ out, int Bn) {
    int c   = blockIdx.x % NCHUNK;
    int b   = blockIdx.x / NCHUNK;
    if (b >= Bn) return;
    int tid = threadIdx.x;
    int ddv = tid & 127;          // 0..127
    int kh  = tid >> 7;           // 0..1
    int dd  = ddv * 4;
    int g   = c >> 4, i = c & 15;

    float2 a2 = make_float2(sigmoid_clip_f(raw_alpha[kh * 2]),
                            sigmoid_clip_f(raw_alpha[kh * 2 + 1]));

    // pL = alpha^16, Q = alpha^256, qp = pL^i  (register-only)
    float2 pL = a2;
#pragma unroll
    for (int s = 0; s < 4; s++) { pL.x *= pL.x; pL.y *= pL.y; }
    float2 Q = pL;
#pragma unroll
    for (int s = 0; s < 4; s++) { Q.x *= Q.x; Q.y *= Q.y; }
    float2 qp = make_float2(1.f, 1.f);
    for (int it = 0; it < i; it++) { qp.x *= pL.x; qp.y *= pL.y; }

    // Inline group carry: C = sum_{g'<g} Q^{g-1-g'} * G[g']  (Horner)
    float2 C0 = make_float2(0.f, 0.f), C1 = C0, C2 = C0, C3 = C0;
    for (int gp = 0; gp < g; gp++) {
        const float* Gb = &g_G[(((size_t)b * NGROUP + gp) * D_DIM + dd) * K_DIM + kh * 2];
        float2 s0 = *(const float2*)(Gb + 0);
        float2 s1 = *(const float2*)(Gb + 4);
        float2 s2 = *(const float2*)(Gb + 8);
        float2 s3 = *(const float2*)(Gb + 12);
        C0.x = fmaf(Q.x, C0.x, s0.x); C0.y = fmaf(Q.y, C0.y, s0.y);
        C1.x = fmaf(Q.x, C1.x, s1.x); C1.y = fmaf(Q.y, C1.y, s1.y);
        C2.x = fmaf(Q.x, C2.x, s2.x); C2.y = fmaf(Q.y, C2.y, s2.y);
        C3.x = fmaf(Q.x, C3.x, s3.x); C3.y = fmaf(Q.y, C3.y, s3.y);
    }

    // S_init = L + C * q^i
    const float* Lb = &g_E[(((size_t)b * NCHUNK + c) * D_DIM + dd) * K_DIM + kh * 2];
    float2 S0, S1, S2, S3;
    {
        float2 L0 = *(const float2*)(Lb + 0);
        float2 L1 = *(const float2*)(Lb + 4);
        float2 L2 = *(const float2*)(Lb + 8);
        float2 L3 = *(const float2*)(Lb + 12);
        S0 = make_float2(fmaf(C0.x, qp.x, L0.x), fmaf(C0.y, qp.y, L0.y));
        S1 = make_float2(fmaf(C1.x, qp.x, L1.x), fmaf(C1.y, qp.y, L1.y));
        S2 = make_float2(fmaf(C2.x, qp.x, L2.x), fmaf(C2.y, qp.y, L2.y));
        S3 = make_float2(fmaf(C3.x, qp.x, L3.x), fmaf(C3.y, qp.y, L3.y));
    }

    const float* hp = h + ((size_t)b * T_DIM + (size_t)c * CHUNK_L) * D_DIM + dd;
    float*       op = out + (((size_t)b * T_DIM + (size_t)c * CHUNK_L) * K_DIM + kh * 2) * D_DIM + dd;
    const float* rp = &g_rtab[((size_t)c * CHUNK_L) * K_DIM + kh * 2];

#pragma unroll
    for (int j = 0; j < CHUNK_L; j++) {
        float4 h4 = *(const float4*)(hp + (size_t)j * D_DIM);
        float2 r2 = make_float2(__ldg(rp + j * K_DIM), __ldg(rp + j * K_DIM + 1));

        S0.x = fmaf(a2.x, S0.x, h4.x); S0.y = fmaf(a2.y, S0.y, h4.x);
        S1.x = fmaf(a2.x, S1.x, h4.y); S1.y = fmaf(a2.y, S1.y, h4.y);
        S2.x = fmaf(a2.x, S2.x, h4.z); S2.y = fmaf(a2.y, S2.y, h4.z);
        S3.x = fmaf(a2.x, S3.x, h4.w); S3.y = fmaf(a2.y, S3.y, h4.w);

        float4 olo = make_float4(S0.x * r2.x, S1.x * r2.x, S2.x * r2.x, S3.x * r2.x);
        float4 ohi = make_float4(S0.y * r2.y, S1.y * r2.y, S2.y * r2.y, S3.y * r2.y);

        float* ob = op + (size_t)j * K_DIM * D_DIM;
        __stcs((float4*)(ob + 0 * D_DIM), olo);
        __stcs((float4*)(ob + 1 * D_DIM), ohi);
    }
}

// ---------------------------------------------------------------------------
extern "C" void kernel_launch(void* const* d_in, const int* in_sizes, int n_in,
                              void* d_out, int out_size) {
    const float* h         = (const float*)d_in[0];
    const float* raw_alpha = (const float*)d_in[1];
    int h_elems = in_sizes[0];
    if (n_in >= 2 && in_sizes[1] > in_sizes[0]) {
        h         = (const float*)d_in[1];
        raw_alpha = (const float*)d_in[0];
        h_elems   = in_sizes[1];
    }
    float* out = (float*)d_out;

    int Bn = h_elems / (T_DIM * D_DIM);
    if (Bn > B_MAX) Bn = B_MAX;
    if (Bn < 1)     Bn = 1;

    { int total = Bn * NCHUNK * (D_DIM / 4);           // covers T_DIM for table side-job
      kB_fused<<<(total + 255) / 256, 256>>>(h, raw_alpha, Bn); }

    { int total = Bn * NGROUP * D_DIM;
      kC_local<<<(total + 255) / 256, 256>>>(raw_alpha, Bn); }

    kD_final<<<Bn * NCHUNK, 256>>>(h, raw_alpha, out, Bn);
}

// round 12
// speedup vs baseline: 1.2642x; 1.2642x over previous
#include <cuda_runtime.h>
#include <math.h>

// h (B=4, T=4096, d=512) fp32, raw_alpha (K=4) fp32 -> out (B, T, K, d) fp32
#define T_DIM 4096
#define D_DIM 512
#define K_DIM 4
#define B_MAX 4
#define CHUNK_L 16
#define NCHUNK (T_DIM / CHUNK_L)   // 256
#define GROUP 16
#define NGROUP (NCHUNK / GROUP)    // 16
#define DDL 16                     // dd-lanes per kC block

// Scratch (allocation-free: __device__ globals)
__device__ float g_rtab[T_DIM * K_DIM];                    // r[t][k] (fp32, expm1-accurate)
__device__ float g_E[B_MAX * NCHUNK * D_DIM * K_DIM];      // chunk sums -> FULL carries (8MB)

__device__ __forceinline__ float sigmoid_clip_f(float x) {
    float a = 1.0f / (1.0f + expf(-x));
    return fminf(fmaxf(a, 1e-6f), 1.0f - 1e-6f);
}

// alpha^16 for all 4 k, fp32, from raw_alpha
__device__ __forceinline__ float4 alpha4_of(const float* ra) {
    return make_float4(sigmoid_clip_f(ra[0]), sigmoid_clip_f(ra[1]),
                       sigmoid_clip_f(ra[2]), sigmoid_clip_f(ra[3]));
}

// ---------------------------------------------------------------------------
// K1 kB: per-chunk local scans -> chunk sums E[b][c][dd][k]
// Thread: (b, c, dd4) — 4 d-lanes x 4 k in regs.
// ---------------------------------------------------------------------------
__global__ __launch_bounds__(256) void kB_chunks(const float* __restrict__ h,
                                                 const float* __restrict__ raw_alpha,
                                                 int Bn) {
    const int DV  = D_DIM / 4;
    int tid = blockIdx.x * blockDim.x + threadIdx.x;
    int ddv = tid % DV;
    int c   = (tid / DV) % NCHUNK;
    int b   = tid / (DV * NCHUNK);
    if (b >= Bn) return;
    int dd = ddv * 4;

    const float4 a4 = alpha4_of(raw_alpha);
    float4 S0 = make_float4(0.f, 0.f, 0.f, 0.f);
    float4 S1 = S0, S2 = S0, S3 = S0;

    const float4* hp = (const float4*)(h + ((size_t)b * T_DIM + (size_t)c * CHUNK_L) * D_DIM + dd);

#pragma unroll
    for (int j = 0; j < CHUNK_L; j++) {
        float4 h4 = hp[(size_t)j * DV];
        S0.x = fmaf(a4.x, S0.x, h4.x); S0.y = fmaf(a4.y, S0.y, h4.x);
        S0.z = fmaf(a4.z, S0.z, h4.x); S0.w = fmaf(a4.w, S0.w, h4.x);
        S1.x = fmaf(a4.x, S1.x, h4.y); S1.y = fmaf(a4.y, S1.y, h4.y);
        S1.z = fmaf(a4.z, S1.z, h4.y); S1.w = fmaf(a4.w, S1.w, h4.y);
        S2.x = fmaf(a4.x, S2.x, h4.z); S2.y = fmaf(a4.y, S2.y, h4.z);
        S2.z = fmaf(a4.z, S2.z, h4.z); S2.w = fmaf(a4.w, S2.w, h4.z);
        S3.x = fmaf(a4.x, S3.x, h4.w); S3.y = fmaf(a4.y, S3.y, h4.w);
        S3.z = fmaf(a4.z, S3.z, h4.w); S3.w = fmaf(a4.w, S3.w, h4.w);
    }

    float4* Ep = (float4*)&g_E[(((size_t)b * NCHUNK + c) * D_DIM + dd) * K_DIM];
    Ep[0] = S0; Ep[1] = S1; Ep[2] = S2; Ep[3] = S3;
}

// ---------------------------------------------------------------------------
// K2 kC: convert chunk sums into FULL carries, in place.
// Block = (b, 16-dd-lane tile). Thread = (g, ddl): one dd-lane (float4 over k),
// one group of 16 chunks. Snapshots kept in registers; group sums scanned in
// smem; E[c] := GC*q^i + P_{i-1}.   Also: fp32 r-table side job.
// ---------------------------------------------------------------------------
__global__ __launch_bounds__(256) void kC_carry(const float* __restrict__ raw_alpha, int Bn) {
    __shared__ float4 gs[GROUP][DDL];

    // side job: r-table (fp32, cancellation-safe). 32768 threads cover T_DIM.
    int gtid = blockIdx.x * blockDim.x + threadIdx.x;
    if (gtid < T_DIM) {
        int t = gtid;
#pragma unroll
        for (int k = 0; k < K_DIM; k++) {
            float oma = 1.0f / (1.0f + expf(raw_alpha[k]));        // 1 - sigmoid(x), exact small
            oma = fminf(fmaxf(oma, 1e-6f), 1.0f - 1e-6f);
            float la  = log1pf(-oma);                              // log(alpha)
            float den = -expm1f((float)(t + 1) * la);              // 1 - alpha^{t+1}
            g_rtab[t * K_DIM + k] = oma / den;
        }
    }

    int tid = threadIdx.x;
    int ddl = tid % DDL;                 // 0..15
    int g   = tid / DDL;                 // 0..15
    int ddt = blockIdx.x % (D_DIM / DDL);
    int b   = blockIdx.x / (D_DIM / DDL);
    if (b >= Bn) return;
    int dd  = ddt * DDL + ddl;

    float4 q = alpha4_of(raw_alpha);
#pragma unroll
    for (int s = 0; s < 4; s++) { q.x *= q.x; q.y *= q.y; q.z *= q.z; q.w *= q.w; } // alpha^16
    float4 Q = q;
#pragma unroll
    for (int s = 0; s < 4; s++) { Q.x *= Q.x; Q.y *= Q.y; Q.z *= Q.z; Q.w *= Q.w; } // alpha^256

    // pass 1: local inclusive scan over this group's 16 chunk sums
    float4* Ep = (float4*)&g_E[(((size_t)b * NCHUNK + (size_t)g * GROUP) * D_DIM + dd) * K_DIM] ;
    // float4 index stride between chunks: D_DIM (since layout is (c*D_DIM+dd) float4s)
    float4 snap[GROUP];
    float4 P = make_float4(0.f, 0.f, 0.f, 0.f);
#pragma unroll
    for (int i = 0; i < GROUP; i++) {
        float4 e = Ep[(size_t)i * D_DIM];
        P.x = fmaf(q.x, P.x, e.x);
        P.y = fmaf(q.y, P.y, e.y);
        P.z = fmaf(q.z, P.z, e.z);
        P.w = fmaf(q.w, P.w, e.w);
        snap[i] = P;
    }
    gs[g][ddl] = P;   // group sum
    __syncthreads();

    // exclusive scan over group sums (16 threads, one per dd-lane)
    if (g == 0) {
        float4 carry = make_float4(0.f, 0.f, 0.f, 0.f);
#pragma unroll
        for (int gg = 0; gg < GROUP; gg++) {
            float4 s = gs[gg][ddl];
            gs[gg][ddl] = carry;
            carry.x = fmaf(Q.x, carry.x, s.x);
            carry.y = fmaf(Q.y, carry.y, s.y);
            carry.z = fmaf(Q.z, carry.z, s.z);
            carry.w = fmaf(Q.w, carry.w, s.w);
        }
    }
    __syncthreads();

    // pass 2: E[c] := GC*q^i + P_{i-1}
    float4 gc = gs[g][ddl];
    float4 prevP = make_float4(0.f, 0.f, 0.f, 0.f);
#pragma unroll
    for (int i = 0; i < GROUP; i++) {
        Ep[(size_t)i * D_DIM] = make_float4(gc.x + prevP.x, gc.y + prevP.y,
                                            gc.z + prevP.z, gc.w + prevP.w);
        gc.x *= q.x; gc.y *= q.y; gc.z *= q.z; gc.w *= q.w;
        prevP = snap[i];
    }
}

// ---------------------------------------------------------------------------
// K3 kD: final scan + normalize + store. Thread = (b, c, kh, dd4).
// S_init read directly from E (full carries). No extra traffic.
// ---------------------------------------------------------------------------
__global__ __launch_bounds__(256) void kD_final(const float* __restrict__ h,
                                                const float* __restrict__ raw_alpha,
                                                float* __restrict__ out, int Bn) {
    int c   = blockIdx.x % NCHUNK;
    int b   = blockIdx.x / NCHUNK;
    if (b >= Bn) return;
    int tid = threadIdx.x;
    int ddv = tid & 127;          // 0..127
    int kh  = tid >> 7;           // 0..1
    int dd  = ddv * 4;

    float2 a2 = make_float2(sigmoid_clip_f(raw_alpha[kh * 2]),
                            sigmoid_clip_f(raw_alpha[kh * 2 + 1]));

    const float* Lb = &g_E[(((size_t)b * NCHUNK + c) * D_DIM + dd) * K_DIM + kh * 2];
    float2 S0 = *(const float2*)(Lb + 0);
    float2 S1 = *(const float2*)(Lb + 4);
    float2 S2 = *(const float2*)(Lb + 8);
    float2 S3 = *(const float2*)(Lb + 12);

    const float* hp = h + ((size_t)b * T_DIM + (size_t)c * CHUNK_L) * D_DIM + dd;
    float*       op = out + (((size_t)b * T_DIM + (size_t)c * CHUNK_L) * K_DIM + kh * 2) * D_DIM + dd;
    const float* rp = &g_rtab[((size_t)c * CHUNK_L) * K_DIM + kh * 2];

#pragma unroll
    for (int j = 0; j < CHUNK_L; j++) {
        float4 h4 = *(const float4*)(hp + (size_t)j * D_DIM);
        float2 r2 = make_float2(__ldg(rp + j * K_DIM), __ldg(rp + j * K_DIM + 1));

        S0.x = fmaf(a2.x, S0.x, h4.x); S0.y = fmaf(a2.y, S0.y, h4.x);
        S1.x = fmaf(a2.x, S1.x, h4.y); S1.y = fmaf(a2.y, S1.y, h4.y);
        S2.x = fmaf(a2.x, S2.x, h4.z); S2.y = fmaf(a2.y, S2.y, h4.z);
        S3.x = fmaf(a2.x, S3.x, h4.w); S3.y = fmaf(a2.y, S3.y, h4.w);

        float4 olo = make_float4(S0.x * r2.x, S1.x * r2.x, S2.x * r2.x, S3.x * r2.x);
        float4 ohi = make_float4(S0.y * r2.y, S1.y * r2.y, S2.y * r2.y, S3.y * r2.y);

        float* ob = op + (size_t)j * K_DIM * D_DIM;
        __stcs((float4*)(ob + 0 * D_DIM), olo);
        __stcs((float4*)(ob + 1 * D_DIM), ohi);
    }
}

// ---------------------------------------------------------------------------
extern "C" void kernel_launch(void* const* d_in, const int* in_sizes, int n_in,
                              void* d_out, int out_size) {
    const float* h         = (const float*)d_in[0];
    const float* raw_alpha = (const float*)d_in[1];
    int h_elems = in_sizes[0];
    if (n_in >= 2 && in_sizes[1] > in_sizes[0]) {
        h         = (const float*)d_in[1];
        raw_alpha = (const float*)d_in[0];
        h_elems   = in_sizes[1];
    }
    float* out = (float*)d_out;

    int Bn = h_elems / (T_DIM * D_DIM);
    if (Bn > B_MAX) Bn = B_MAX;
    if (Bn < 1)     Bn = 1;

    { int total = Bn * NCHUNK * (D_DIM / 4);
      kB_chunks<<<(total + 255) / 256, 256>>>(h, raw_alpha, Bn); }

    kC_carry<<<Bn * (D_DIM / DDL), 256>>>(raw_alpha, Bn);

    kD_final<<<Bn * NCHUNK, 256>>>(h, raw_alpha, out, Bn);
}

// round 15
// speedup vs baseline: 1.3185x; 1.0430x over previous
#include <cuda_runtime.h>
#include <math.h>

// h (B=4, T=4096, d=512) fp32, raw_alpha (K=4) fp32 -> out (B, T, K, d) fp32
#define T_DIM 4096
#define D_DIM 512
#define K_DIM 4
#define B_MAX 4
#define CHUNK_L 16
#define NCHUNK (T_DIM / CHUNK_L)   // 256
#define GROUP 16
#define NGROUP (NCHUNK / GROUP)    // 16
#define DDL 16                     // dd-lanes per kC block

// Scratch (allocation-free: __device__ globals)
__device__ float g_rtab[T_DIM * K_DIM];                    // r[t][k] (fp32, expm1-accurate)
__device__ float g_E[B_MAX * NCHUNK * D_DIM * K_DIM];      // chunk sums -> FULL carries (8MB)

__device__ __forceinline__ float sigmoid_clip_f(float x) {
    float a = 1.0f / (1.0f + expf(-x));
    return fminf(fmaxf(a, 1e-6f), 1.0f - 1e-6f);
}

__device__ __forceinline__ float4 alpha4_of(const float* ra) {
    return make_float4(sigmoid_clip_f(ra[0]), sigmoid_clip_f(ra[1]),
                       sigmoid_clip_f(ra[2]), sigmoid_clip_f(ra[3]));
}

// ---------------------------------------------------------------------------
// K1 kB: per-chunk local scans -> chunk sums E[b][c][dd][k]
// Split for occupancy/MLP: thread = (b, c, dd2) — 2 d-lanes x 4 k in regs.
// 262144 threads, 1024 blocks.
// ---------------------------------------------------------------------------
__global__ __launch_bounds__(256) void kB_chunks(const float* __restrict__ h,
                                                 const float* __restrict__ raw_alpha,
                                                 int Bn) {
    const int DV2 = D_DIM / 2;   // 256 d-pairs
    int tid  = blockIdx.x * blockDim.x + threadIdx.x;
    int ddp  = tid % DV2;
    int c    = (tid / DV2) % NCHUNK;
    int b    = tid / (DV2 * NCHUNK);
    if (b >= Bn) return;
    int dd = ddp * 2;

    const float4 a4 = alpha4_of(raw_alpha);
    float4 S0 = make_float4(0.f, 0.f, 0.f, 0.f);   // d-lane dd,   k=0..3
    float4 S1 = S0;                                 // d-lane dd+1, k=0..3

    const float2* hp = (const float2*)(h + ((size_t)b * T_DIM + (size_t)c * CHUNK_L) * D_DIM + dd);

#pragma unroll
    for (int j = 0; j < CHUNK_L; j++) {
        float2 h2 = hp[(size_t)j * DV2];
        S0.x = fmaf(a4.x, S0.x, h2.x); S0.y = fmaf(a4.y, S0.y, h2.x);
        S0.z = fmaf(a4.z, S0.z, h2.x); S0.w = fmaf(a4.w, S0.w, h2.x);
        S1.x = fmaf(a4.x, S1.x, h2.y); S1.y = fmaf(a4.y, S1.y, h2.y);
        S1.z = fmaf(a4.z, S1.z, h2.y); S1.w = fmaf(a4.w, S1.w, h2.y);
    }

    float4* Ep = (float4*)&g_E[(((size_t)b * NCHUNK + c) * D_DIM + dd) * K_DIM];
    Ep[0] = S0; Ep[1] = S1;
}

// ---------------------------------------------------------------------------
// K2 kC: convert chunk sums into FULL carries, in place.
// Block = (b, 16-dd-lane tile). Thread = (g, ddl). Also: fp32 r-table side job.
// ---------------------------------------------------------------------------
__global__ __launch_bounds__(256) void kC_carry(const float* __restrict__ raw_alpha, int Bn) {
    __shared__ float4 gs[GROUP][DDL];

    // side job: r-table (fp32, cancellation-safe). 32768 threads cover T_DIM.
    int gtid = blockIdx.x * blockDim.x + threadIdx.x;
    if (gtid < T_DIM) {
        int t = gtid;
#pragma unroll
        for (int k = 0; k < K_DIM; k++) {
            float oma = 1.0f / (1.0f + expf(raw_alpha[k]));        // 1 - sigmoid(x)
            oma = fminf(fmaxf(oma, 1e-6f), 1.0f - 1e-6f);
            float la  = log1pf(-oma);                              // log(alpha)
            float den = -expm1f((float)(t + 1) * la);              // 1 - alpha^{t+1}
            g_rtab[t * K_DIM + k] = oma / den;
        }
    }

    int tid = threadIdx.x;
    int ddl = tid % DDL;                 // 0..15
    int g   = tid / DDL;                 // 0..15
    int ddt = blockIdx.x % (D_DIM / DDL);
    int b   = blockIdx.x / (D_DIM / DDL);
    if (b >= Bn) return;
    int dd  = ddt * DDL + ddl;

    float4 q = alpha4_of(raw_alpha);
#pragma unroll
    for (int s = 0; s < 4; s++) { q.x *= q.x; q.y *= q.y; q.z *= q.z; q.w *= q.w; } // alpha^16
    float4 Q = q;
#pragma unroll
    for (int s = 0; s < 4; s++) { Q.x *= Q.x; Q.y *= Q.y; Q.z *= Q.z; Q.w *= Q.w; } // alpha^256

    float4* Ep = (float4*)&g_E[(((size_t)b * NCHUNK + (size_t)g * GROUP) * D_DIM + dd) * K_DIM];
    float4 snap[GROUP];
    float4 P = make_float4(0.f, 0.f, 0.f, 0.f);
#pragma unroll
    for (int i = 0; i < GROUP; i++) {
        float4 e = Ep[(size_t)i * D_DIM];
        P.x = fmaf(q.x, P.x, e.x);
        P.y = fmaf(q.y, P.y, e.y);
        P.z = fmaf(q.z, P.z, e.z);
        P.w = fmaf(q.w, P.w, e.w);
        snap[i] = P;
    }
    gs[g][ddl] = P;   // group sum
    __syncthreads();

    if (g == 0) {
        float4 carry = make_float4(0.f, 0.f, 0.f, 0.f);
#pragma unroll
        for (int gg = 0; gg < GROUP; gg++) {
            float4 s = gs[gg][ddl];
            gs[gg][ddl] = carry;
            carry.x = fmaf(Q.x, carry.x, s.x);
            carry.y = fmaf(Q.y, carry.y, s.y);
            carry.z = fmaf(Q.z, carry.z, s.z);
            carry.w = fmaf(Q.w, carry.w, s.w);
        }
    }
    __syncthreads();

    float4 gc = gs[g][ddl];
    float4 prevP = make_float4(0.f, 0.f, 0.f, 0.f);
#pragma unroll
    for (int i = 0; i < GROUP; i++) {
        Ep[(size_t)i * D_DIM] = make_float4(gc.x + prevP.x, gc.y + prevP.y,
                                            gc.z + prevP.z, gc.w + prevP.w);
        gc.x *= q.x; gc.y *= q.y; gc.z *= q.z; gc.w *= q.w;
        prevP = snap[i];
    }
}

// ---------------------------------------------------------------------------
// K3 kD: final scan + normalize + store. Thread = (b, c, kh, dd4).
// ---------------------------------------------------------------------------
__global__ __launch_bounds__(256) void kD_final(const float* __restrict__ h,
                                                const float* __restrict__ raw_alpha,
                                                float* __restrict__ out, int Bn) {
    int c   = blockIdx.x % NCHUNK;
    int b   = blockIdx.x / NCHUNK;
    if (b >= Bn) return;
    int tid = threadIdx.x;
    int ddv = tid & 127;          // 0..127
    int kh  = tid >> 7;           // 0..1
    int dd  = ddv * 4;

    float2 a2 = make_float2(sigmoid_clip_f(raw_alpha[kh * 2]),
                            sigmoid_clip_f(raw_alpha[kh * 2 + 1]));

    const float* Lb = &g_E[(((size_t)b * NCHUNK + c) * D_DIM + dd) * K_DIM + kh * 2];
    float2 S0 = *(const float2*)(Lb + 0);
    float2 S1 = *(const float2*)(Lb + 4);
    float2 S2 = *(const float2*)(Lb + 8);
    float2 S3 = *(const float2*)(Lb + 12);

    const float* hp = h + ((size_t)b * T_DIM + (size_t)c * CHUNK_L) * D_DIM + dd;
    float*       op = out + (((size_t)b * T_DIM + (size_t)c * CHUNK_L) * K_DIM + kh * 2) * D_DIM + dd;
    const float* rp = &g_rtab[((size_t)c * CHUNK_L) * K_DIM + kh * 2];

#pragma unroll
    for (int j = 0; j < CHUNK_L; j++) {
        float4 h4 = *(const float4*)(hp + (size_t)j * D_DIM);
        float2 r2 = make_float2(__ldg(rp + j * K_DIM), __ldg(rp + j * K_DIM + 1));

        S0.x = fmaf(a2.x, S0.x, h4.x); S0.y = fmaf(a2.y, S0.y, h4.x);
        S1.x = fmaf(a2.x, S1.x, h4.y); S1.y = fmaf(a2.y, S1.y, h4.y);
        S2.x = fmaf(a2.x, S2.x, h4.z); S2.y = fmaf(a2.y, S2.y, h4.z);
        S3.x = fmaf(a2.x, S3.x, h4.w); S3.y = fmaf(a2.y, S3.y, h4.w);

        float4 olo = make_float4(S0.x * r2.x, S1.x * r2.x, S2.x * r2.x, S3.x * r2.x);
        float4 ohi = make_float4(S0.y * r2.y, S1.y * r2.y, S2.y * r2.y, S3.y * r2.y);

        float* ob = op + (size_t)j * K_DIM * D_DIM;
        __stcs((float4*)(ob + 0 * D_DIM), olo);
        __stcs((float4*)(ob + 1 * D_DIM), ohi);
    }
}

// ---------------------------------------------------------------------------
extern "C" void kernel_launch(void* const* d_in, const int* in_sizes, int n_in,
                              void* d_out, int out_size) {
    const float* h         = (const float*)d_in[0];
    const float* raw_alpha = (const float*)d_in[1];
    int h_elems = in_sizes[0];
    if (n_in >= 2 && in_sizes[1] > in_sizes[0]) {
        h         = (const float*)d_in[1];
        raw_alpha = (const float*)d_in[0];
        h_elems   = in_sizes[1];
    }
    float* out = (float*)d_out;

    int Bn = h_elems / (T_DIM * D_DIM);
    if (Bn > B_MAX) Bn = B_MAX;
    if (Bn < 1)     Bn = 1;

    { int total = Bn * NCHUNK * (D_DIM / 2);
      kB_chunks<<<(total + 255) / 256, 256>>>(h, raw_alpha, Bn); }

    kC_carry<<<Bn * (D_DIM / DDL), 256>>>(raw_alpha, Bn);

    kD_final<<<Bn * NCHUNK, 256>>>(h, raw_alpha, out, Bn);
}